// round 10
// baseline (speedup 1.0000x reference)
#include <cuda_runtime.h>
#include <cuda_bf16.h>
#include <math.h>

// Shapes (fixed by the problem)
#define NQ   10
#define NL   4
#define NG   (NL * NQ)   // 40 single-qubit gates
#define NDIM 1024        // 2^NQ amplitudes
#define FFN  4096
#define EDIM 1024
#define NTOK 16384       // B*T
#define GRID_A 148       // 0..7 h, 8..135 y, 136..146 fill-only, 147 circuit

// Persistent flags/scratch; all counters monotonic across graph replays.
__device__ int g_entry = 0;
__device__ int g_zflag = 0;
__device__ int g_hcnt  = 0;
__device__ int g_ycnt  = 0;
__device__ float g_z[16];
__device__ __align__(16) float g_h[FFN];
__device__ __align__(16) float g_y[EDIM];

__device__ __forceinline__ float2 cmul(float2 a, float2 b) {
    return make_float2(fmaf(a.x, b.x, -a.y * b.y), fmaf(a.x, b.y, a.y * b.x));
}
__device__ __forceinline__ float2 cfma2(float2 u, float2 a, float2 v, float2 b) {
    float re = fmaf(u.x, a.x, -u.y * a.y);
    re = fmaf(v.x, b.x, re);
    re = fmaf(-v.y, b.y, re);
    float im = fmaf(u.x, a.y, u.y * a.x);
    im = fmaf(v.x, b.y, im);
    im = fmaf(v.y, b.x, im);
    return make_float2(re, im);
}
__device__ __forceinline__ void l2_prefetch(const void* p) {
    asm volatile("prefetch.global.L2 [%0];" :: "l"(p));
}

// padded smem index for stride-16 gathers
#define SIDX(i) ((i) + ((i) >> 4))
#define STSZ    (NDIM + NDIM / 16 + 8)

// fill chunking: 4M float4 over 147 blocks (circuit block gets none)
#define FILL_TOT   (NTOK * EDIM / 4)        // 4194304 float4
#define FILL_MAIN  28672                    // 56 iters * 512 thr (blocks 0..145)
#define FILL_TAILB 146
#define FILL_TAIL  (FILL_TOT - 146 * FILL_MAIN)   // 8192 -> 16 iters

__device__ __forceinline__ void fill_chunk(float4* __restrict__ out, int b, int t) {
    const float4 v = ((const float4*)g_y)[t & 255];
    if (b < FILL_TAILB) {
        float4* __restrict__ o = out + (size_t)b * FILL_MAIN + t;
        #pragma unroll 8
        for (int i = 0; i < FILL_MAIN / 512; i++) __stcs(o + i * 512, v);
    } else if (b == FILL_TAILB) {
        float4* __restrict__ o = out + (size_t)FILL_TAILB * FILL_MAIN + t;
        #pragma unroll 8
        for (int i = 0; i < FILL_TAIL / 512; i++) __stcs(o + i * 512, v);
    }
}

// ---------------------------------------------------------------------------
// ONE kernel does everything:
//   block 147 : circuit -> g_z (layer 1 computed analytically: product state
//               fused with the first CNOT ring -> no shfl/bar for layer 1)
//   blocks 0..7: W1 rows in regs during circuit -> h -> g_h, bump hcnt
//   blocks 8..135: 8 W2 rows in regs during circuit -> y slice -> g_y, bump ycnt
//   all blocks 0..146: spin ycnt, then stream 1/147 of the 64MB output
// ---------------------------------------------------------------------------
__global__ void __launch_bounds__(512, 1)
fused_kernel(const float* __restrict__ params,
             const float* __restrict__ W1,
             const float* __restrict__ b1,
             const float* __restrict__ W2,
             const float* __restrict__ b2,
             float4* __restrict__ out) {
    __shared__ float2 U[NG][2];
    __shared__ float2 st[2][STSZ];
    __shared__ float  wsum[16][NQ];
    __shared__ float  red[16];
    __shared__ int    s_epoch;

    const int t    = threadIdx.x;          // 0..511
    const int b    = blockIdx.x;
    const int lane = t & 31;
    const int warp = t >> 5;

    if (t == 0) s_epoch = atomicAdd(&g_entry, 1) / GRID_A;
    __syncthreads();
    const int target = s_epoch + 1;

    if (b == GRID_A - 1) {
        // ===================== circuit =====================
        if (t < NG) {
            const float t0 = params[t * 3 + 0];
            const float t1 = params[t * 3 + 1];
            const float t2 = params[t * 3 + 2];
            float cx, sx, cy, sy, cz, sz;
            __sincosf(0.5f * t0, &sx, &cx);
            __sincosf(0.5f * t1, &sy, &cy);
            __sincosf(0.5f * t2, &sz, &cz);
            const float2 m00 = make_float2( cy * cx,  sy * sx);
            const float2 m01 = make_float2(-sy * cx, -cy * sx);
            const float2 ezm = make_float2(cz, -sz);
            U[t][0] = cmul(ezm, m00);   // u00
            U[t][1] = cmul(ezm, m01);   // u01 (u10=-conj(u01), u11=conj(u00))
        }

        // layout-B base: bits[8:5]=lane[4:1], bit4=lane[0], bits[3:0]=warp
        const int iB = ((lane >> 1) << 5) | ((lane & 1) << 4) | warp;

        int Ct0 = t, Ct1 = t + 512;
        #pragma unroll
        for (int e = NQ - 1; e >= 0; e--) {
            const int c  = (e < NQ - 1) ? e : NQ - 1;
            const int tq = (e < NQ - 1) ? e + 1 : 0;
            const int cm = 1 << (NQ - 1 - c);
            const int tm = 1 << (NQ - 1 - tq);
            Ct0 ^= (Ct0 & cm) ? tm : 0;
            Ct1 ^= (Ct1 & cm) ? tm : 0;
        }
        float sgn[5];
        #pragma unroll
        for (int k = 0; k < 5; k++) sgn[k] = (lane & (16 >> k)) ? -1.0f : 1.0f;

        __syncthreads();   // U ready

        // ---- layer 1 analytically: product state |psi> = prod_q (u00,u10)_q,
        //      fused with the first CNOT ring: a(i) = psi(C(i)) ---------------
        float2 a0, a1;
        {
            float2 p0, p1;
            #pragma unroll
            for (int q = 0; q < NQ; q++) {
                const float2 u00 = U[q][0];
                const float2 u01 = U[q][1];
                const float2 u10 = make_float2(-u01.x, u01.y);
                const float2 v0 = ((Ct0 >> (9 - q)) & 1) ? u10 : u00;
                const float2 v1 = ((Ct1 >> (9 - q)) & 1) ? u10 : u00;
                if (q == 0) { p0 = v0; p1 = v1; }
                else        { p0 = cmul(p0, v0); p1 = cmul(p1, v1); }
            }
            a0 = p0; a1 = p1;
        }

        // ---- layers 2..4 -----------------------------------------------------
        int cur = 0;
        #pragma unroll 1
        for (int l = 1; l < NL; l++) {
            // qubit 0: register bit (thread-local)
            {
                const int g = l * NQ;
                const float2 u00 = U[g][0], u01 = U[g][1];
                const float2 u10 = make_float2(-u01.x, u01.y);
                const float2 u11 = make_float2( u00.x, -u00.y);
                const float2 n0 = cfma2(u00, a0, u01, a1);
                const float2 n1 = cfma2(u10, a0, u11, a1);
                a0 = n0; a1 = n1;
            }
            // qubits 5..9 on lane bits (layout A)
            #pragma unroll
            for (int k = 0; k < 5; k++) {
                const int g = l * NQ + 5 + k;
                float2 u0 = U[g][0];
                float2 u1 = U[g][1];
                const float s = sgn[k];
                u0.y *= s; u1.x *= s;
                const int m = 16 >> k;
                float2 b0v, b1v;
                b0v.x = __shfl_xor_sync(0xffffffffu, a0.x, m);
                b0v.y = __shfl_xor_sync(0xffffffffu, a0.y, m);
                b1v.x = __shfl_xor_sync(0xffffffffu, a1.x, m);
                b1v.y = __shfl_xor_sync(0xffffffffu, a1.y, m);
                a0 = cfma2(u0, a0, u1, b0v);
                a1 = cfma2(u0, a1, u1, b1v);
            }
            // transpose A -> B
            st[cur][SIDX(t)]       = a0;
            st[cur][SIDX(t + 512)] = a1;
            __syncthreads();
            a0 = st[cur][SIDX(iB)];
            a1 = st[cur][SIDX(iB + 512)];
            cur ^= 1;
            // qubits 1..4 on lane bits 4..1 (layout B)
            #pragma unroll
            for (int k = 0; k < 4; k++) {
                const int g = l * NQ + 1 + k;
                float2 u0 = U[g][0];
                float2 u1 = U[g][1];
                const float s = sgn[k];
                u0.y *= s; u1.x *= s;
                const int m = 16 >> k;
                float2 b0v, b1v;
                b0v.x = __shfl_xor_sync(0xffffffffu, a0.x, m);
                b0v.y = __shfl_xor_sync(0xffffffffu, a0.y, m);
                b1v.x = __shfl_xor_sync(0xffffffffu, a1.x, m);
                b1v.y = __shfl_xor_sync(0xffffffffu, a1.y, m);
                a0 = cfma2(u0, a0, u1, b0v);
                a1 = cfma2(u0, a1, u1, b1v);
            }
            // CNOT ring + transpose back
            st[cur][SIDX(iB)]       = a0;
            st[cur][SIDX(iB + 512)] = a1;
            __syncthreads();
            a0 = st[cur][SIDX(Ct0)];
            a1 = st[cur][SIDX(Ct1)];
            cur ^= 1;
        }

        // <Z_q>
        const float p0 = fmaf(a0.x, a0.x, a0.y * a0.y);
        const float p1 = fmaf(a1.x, a1.x, a1.y * a1.y);
        #pragma unroll
        for (int q = 0; q < NQ; q++) {
            float v;
            if (q == 0) {
                v = p1;
            } else {
                const int mask = 1 << (NQ - 1 - q);
                v = (t & mask) ? (p0 + p1) : 0.0f;
            }
            #pragma unroll
            for (int o = 16; o > 0; o >>= 1) v += __shfl_xor_sync(0xffffffffu, v, o);
            if (lane == 0) wsum[warp][q] = v;
        }
        __syncthreads();
        if (t < NQ) {
            float s = 0.0f;
            #pragma unroll
            for (int w = 0; w < 16; w++) s += wsum[w][t];
            g_z[t] = 1.0f - 2.0f * s;
        }
        __syncthreads();
        if (t == 0) {
            __threadfence();
            atomicMax(&g_zflag, target);   // release; monotonic
        }
        return;   // circuit block takes no fill share (it finishes last)
    }

    if (b < 8) {
        // ============ h rows: W1 row in regs while circuit runs ============
        const int j = b * 512 + t;
        const float* __restrict__ w = W1 + (size_t)j * NQ;
        float f[NQ];
        #pragma unroll
        for (int q = 0; q < NQ; q++) f[q] = w[q];
        const float bias = b1[j];

        if (t == 0) {
            while (((volatile int*)&g_zflag)[0] < target) __nanosleep(32);
        }
        __syncthreads();
        __threadfence();

        float acc = bias;
        #pragma unroll
        for (int q = 0; q < NQ; q++) acc = fmaf(f[q], g_z[q], acc);
        g_h[j] = fmaxf(acc, 0.0f);
        __threadfence();
        __syncthreads();
        if (t == 0) atomicAdd(&g_hcnt, 1);
    } else if (b < 136) {
        // ========= y blocks: y[8pb..8pb+8), W2 rows preloaded =========
        const int pb = b - 8;                     // 0..127
        const int g  = t >> 6;                    // 0..7
        const int j  = t & 63;
        const int e  = pb * 8 + g;
        const float4* __restrict__ w4 = (const float4*)(W2 + (size_t)e * FFN);

        #pragma unroll
        for (int k = 0; k < 16; k++) l2_prefetch(&w4[j + 64 * k]);
        if (t == 0) l2_prefetch(b2 + pb * 8);
        float4 w[16];
        #pragma unroll
        for (int k = 0; k < 16; k++) w[k] = w4[j + 64 * k];

        if (t == 0) {
            const int ht = 8 * target;
            while (((volatile int*)&g_hcnt)[0] < ht) __nanosleep(32);
        }
        __syncthreads();
        __threadfence();

        const float4* __restrict__ h4 = (const float4*)g_h;
        float acc = 0.0f;
        #pragma unroll
        for (int k = 0; k < 16; k++) {
            const float4 h = h4[j + 64 * k];
            acc += w[k].x * h.x + w[k].y * h.y + w[k].z * h.z + w[k].w * h.w;
        }
        #pragma unroll
        for (int o = 16; o > 0; o >>= 1) acc += __shfl_down_sync(0xffffffffu, acc, o);
        if (lane == 0) red[warp] = acc;
        __syncthreads();
        if (t < 8) g_y[pb * 8 + t] = red[2 * t] + red[2 * t + 1] + b2[pb * 8 + t];
        __threadfence();
        __syncthreads();
        if (t == 0) atomicAdd(&g_ycnt, 1);
    }
    // blocks 136..146 fall through directly to the fill wait

    // ============ all non-circuit blocks: wait for full y, then fill ========
    if (t == 0) {
        const int yt = 128 * target;
        while (((volatile int*)&g_ycnt)[0] < yt) __nanosleep(32);
    }
    __syncthreads();
    __threadfence();

    fill_chunk(out, b, t);
}

// ---------------------------------------------------------------------------
// inputs: 0=x, 1=W_in, 2=b_in, 3=params, 4=W1, 5=b1, 6=W2, 7=b2
// x / W_in / b_in are dead in the reference.
// ---------------------------------------------------------------------------
extern "C" void kernel_launch(void* const* d_in, const int* in_sizes, int n_in,
                              void* d_out, int out_size) {
    const float* params = (const float*)d_in[3];
    const float* W1     = (const float*)d_in[4];
    const float* b1     = (const float*)d_in[5];
    const float* W2     = (const float*)d_in[6];
    const float* b2     = (const float*)d_in[7];
    float4* out = (float4*)d_out;

    fused_kernel<<<GRID_A, 512>>>(params, W1, b1, W2, b2, out);
}

// round 11
// speedup vs baseline: 1.0737x; 1.0737x over previous
#include <cuda_runtime.h>
#include <cuda_bf16.h>
#include <math.h>

// Shapes (fixed by the problem)
#define NQ   10
#define NL   4
#define NG   (NL * NQ)   // 40 single-qubit gates
#define NDIM 1024        // 2^NQ amplitudes
#define FFN  4096
#define EDIM 1024
#define NTOK 16384       // B*T
#define GRID_A 137       // 0..7 h-rows, 8..135 matvec (128), 136 circuit

// Persistent scratch / flags (monotonic across graph replays: no reset needed)
__device__ int g_entry = 0;
__device__ int g_zflag = 0;
__device__ int g_hcnt  = 0;
__device__ float g_z[16];
__device__ __align__(16) float g_h[FFN];
__device__ __align__(16) float g_y[EDIM];

__device__ __forceinline__ float2 cmul(float2 a, float2 b) {
    return make_float2(fmaf(a.x, b.x, -a.y * b.y), fmaf(a.x, b.y, a.y * b.x));
}
__device__ __forceinline__ float2 cfma2(float2 u, float2 a, float2 v, float2 b) {
    float re = fmaf(u.x, a.x, -u.y * a.y);
    re = fmaf(v.x, b.x, re);
    re = fmaf(-v.y, b.y, re);
    float im = fmaf(u.x, a.y, u.y * a.x);
    im = fmaf(v.x, b.y, im);
    im = fmaf(v.y, b.x, im);
    return make_float2(re, im);
}
__device__ __forceinline__ void l2_prefetch(const void* p) {
    asm volatile("prefetch.global.L2 [%0];" :: "l"(p));
}

// padded smem index for stride-16 gathers
#define SIDX(i) ((i) + ((i) >> 4))
#define STSZ    (NDIM + NDIM / 16 + 8)

// ---------------------------------------------------------------------------
// Kernel A (everything except the fill):
//   block 136 : circuit -> g_z. Layer 1 is computed ANALYTICALLY: acting on
//               |0..0>, the first rotation layer yields a product state
//               psi(i) = prod_q (bit_q(i) ? u10_q : u00_q); we evaluate it
//               directly at the first-CNOT-ring-permuted index -> layer 1
//               costs ~100 FMAs, no shfl/smem/barriers.
//   blocks 0..7: W1 rows in regs during circuit -> h = relu(W1 z+b1) -> g_h
//   blocks 8..135: own 8 W2 rows in regs during circuit -> y slice -> g_y
// ---------------------------------------------------------------------------
__global__ void __launch_bounds__(512, 1)
circuit_h_y_kernel(const float* __restrict__ params,
                   const float* __restrict__ W1,
                   const float* __restrict__ b1,
                   const float* __restrict__ W2,
                   const float* __restrict__ b2) {
    __shared__ float2 U[NG][2];
    __shared__ float2 st[2][STSZ];
    __shared__ float  wsum[16][NQ];
    __shared__ float  red[16];
    __shared__ int    s_epoch;

    const int t    = threadIdx.x;          // 0..511
    const int b    = blockIdx.x;
    const int lane = t & 31;
    const int warp = t >> 5;

    if (t == 0) s_epoch = atomicAdd(&g_entry, 1) / GRID_A;
    __syncthreads();
    const int target = s_epoch + 1;

    if (b < 8) {
        // ============ h rows: W1 row in regs while circuit runs ============
        const int j = b * 512 + t;               // row 0..4095
        const float* __restrict__ w = W1 + (size_t)j * NQ;
        float f[NQ];
        #pragma unroll
        for (int q = 0; q < NQ; q++) f[q] = w[q];
        const float bias = b1[j];

        if (t == 0) {
            while (((volatile int*)&g_zflag)[0] < target) __nanosleep(32);
        }
        __syncthreads();
        __threadfence();

        float acc = bias;
        #pragma unroll
        for (int q = 0; q < NQ; q++) acc = fmaf(f[q], g_z[q], acc);
        g_h[j] = fmaxf(acc, 0.0f);
        __threadfence();
        __syncthreads();
        if (t == 0) atomicAdd(&g_hcnt, 1);
        return;
    }

    if (b < 136) {
        // ========= matvec blocks: y[8pb .. 8pb+8), W2 rows preloaded =========
        const int pb = b - 8;                     // 0..127
        const int g  = t >> 6;                    // 0..7 output within block
        const int j  = t & 63;
        const int e  = pb * 8 + g;
        const float4* __restrict__ w4 = (const float4*)(W2 + (size_t)e * FFN);

        #pragma unroll
        for (int k = 0; k < 16; k++) l2_prefetch(&w4[j + 64 * k]);
        if (t == 0) l2_prefetch(b2 + pb * 8);
        float4 w[16];
        #pragma unroll
        for (int k = 0; k < 16; k++) w[k] = w4[j + 64 * k];

        // wait for all 8 h blocks
        if (t == 0) {
            const int ht = 8 * target;
            while (((volatile int*)&g_hcnt)[0] < ht) __nanosleep(32);
        }
        __syncthreads();
        __threadfence();

        const float4* __restrict__ h4 = (const float4*)g_h;
        float acc = 0.0f;
        #pragma unroll
        for (int k = 0; k < 16; k++) {
            const float4 h = h4[j + 64 * k];
            acc += w[k].x * h.x + w[k].y * h.y + w[k].z * h.z + w[k].w * h.w;
        }
        #pragma unroll
        for (int o = 16; o > 0; o >>= 1) acc += __shfl_down_sync(0xffffffffu, acc, o);
        if (lane == 0) red[warp] = acc;
        __syncthreads();
        if (t < 8) g_y[pb * 8 + t] = red[2 * t] + red[2 * t + 1] + b2[pb * 8 + t];
        return;
    }

    // ===================== circuit (block 136) =====================
    if (t < NG) {
        const float t0 = params[t * 3 + 0];
        const float t1 = params[t * 3 + 1];
        const float t2 = params[t * 3 + 2];
        float cx, sx, cy, sy, cz, sz;
        sincosf(0.5f * t0, &sx, &cx);
        sincosf(0.5f * t1, &sy, &cy);
        sincosf(0.5f * t2, &sz, &cz);
        const float2 m00 = make_float2( cy * cx,  sy * sx);
        const float2 m01 = make_float2(-sy * cx, -cy * sx);
        const float2 ezm = make_float2(cz, -sz);
        U[t][0] = cmul(ezm, m00);   // u00
        U[t][1] = cmul(ezm, m01);   // u01 (u10=-conj(u01), u11=conj(u00))
    }

    // layout-B base index: bits[8:5]=lane[4:1], bit4=lane[0], bits[3:0]=warp
    const int iB = ((lane >> 1) << 5) | ((lane & 1) << 4) | warp;

    int Ct0 = t, Ct1 = t + 512;
    #pragma unroll
    for (int e = NQ - 1; e >= 0; e--) {
        const int c  = (e < NQ - 1) ? e : NQ - 1;
        const int tq = (e < NQ - 1) ? e + 1 : 0;
        const int cm = 1 << (NQ - 1 - c);
        const int tm = 1 << (NQ - 1 - tq);
        Ct0 ^= (Ct0 & cm) ? tm : 0;
        Ct1 ^= (Ct1 & cm) ? tm : 0;
    }
    float sgn[5];
    #pragma unroll
    for (int k = 0; k < 5; k++) sgn[k] = (lane & (16 >> k)) ? -1.0f : 1.0f;

    __syncthreads();   // U ready

    // ---- layer 1 analytic: a(i) = psi(C(i)), psi = product state ----------
    float2 a0, a1;
    {
        float2 p0, p1;
        #pragma unroll
        for (int q = 0; q < NQ; q++) {
            const float2 u00 = U[q][0];
            const float2 u01 = U[q][1];
            const float2 u10 = make_float2(-u01.x, u01.y);
            const float2 v0 = ((Ct0 >> (9 - q)) & 1) ? u10 : u00;
            const float2 v1 = ((Ct1 >> (9 - q)) & 1) ? u10 : u00;
            if (q == 0) { p0 = v0; p1 = v1; }
            else        { p0 = cmul(p0, v0); p1 = cmul(p1, v1); }
        }
        a0 = p0; a1 = p1;
    }

    // ---- layers 2..4 ------------------------------------------------------
    int cur = 0;
    #pragma unroll 1
    for (int l = 1; l < NL; l++) {
        // qubit 0: register bit (thread-local)
        {
            const int g = l * NQ;
            const float2 u00 = U[g][0], u01 = U[g][1];
            const float2 u10 = make_float2(-u01.x, u01.y);
            const float2 u11 = make_float2( u00.x, -u00.y);
            const float2 n0 = cfma2(u00, a0, u01, a1);
            const float2 n1 = cfma2(u10, a0, u11, a1);
            a0 = n0; a1 = n1;
        }
        // qubits 5..9 on lane bits (layout A)
        #pragma unroll
        for (int k = 0; k < 5; k++) {
            const int g = l * NQ + 5 + k;
            float2 u0 = U[g][0];
            float2 u1 = U[g][1];
            const float s = sgn[k];
            u0.y *= s; u1.x *= s;
            const int m = 16 >> k;
            float2 b0v, b1v;
            b0v.x = __shfl_xor_sync(0xffffffffu, a0.x, m);
            b0v.y = __shfl_xor_sync(0xffffffffu, a0.y, m);
            b1v.x = __shfl_xor_sync(0xffffffffu, a1.x, m);
            b1v.y = __shfl_xor_sync(0xffffffffu, a1.y, m);
            a0 = cfma2(u0, a0, u1, b0v);
            a1 = cfma2(u0, a1, u1, b1v);
        }
        // transpose A -> B
        st[cur][SIDX(t)]       = a0;
        st[cur][SIDX(t + 512)] = a1;
        __syncthreads();
        a0 = st[cur][SIDX(iB)];
        a1 = st[cur][SIDX(iB + 512)];
        cur ^= 1;
        // qubits 1..4 on lane bits 4..1 (layout B)
        #pragma unroll
        for (int k = 0; k < 4; k++) {
            const int g = l * NQ + 1 + k;
            float2 u0 = U[g][0];
            float2 u1 = U[g][1];
            const float s = sgn[k];
            u0.y *= s; u1.x *= s;
            const int m = 16 >> k;
            float2 b0v, b1v;
            b0v.x = __shfl_xor_sync(0xffffffffu, a0.x, m);
            b0v.y = __shfl_xor_sync(0xffffffffu, a0.y, m);
            b1v.x = __shfl_xor_sync(0xffffffffu, a1.x, m);
            b1v.y = __shfl_xor_sync(0xffffffffu, a1.y, m);
            a0 = cfma2(u0, a0, u1, b0v);
            a1 = cfma2(u0, a1, u1, b1v);
        }
        // CNOT ring + transpose back
        st[cur][SIDX(iB)]       = a0;
        st[cur][SIDX(iB + 512)] = a1;
        __syncthreads();
        a0 = st[cur][SIDX(Ct0)];
        a1 = st[cur][SIDX(Ct1)];
        cur ^= 1;
    }

    // <Z_q>
    const float p0 = fmaf(a0.x, a0.x, a0.y * a0.y);
    const float p1 = fmaf(a1.x, a1.x, a1.y * a1.y);
    #pragma unroll
    for (int q = 0; q < NQ; q++) {
        float v;
        if (q == 0) {
            v = p1;
        } else {
            const int mask = 1 << (NQ - 1 - q);
            v = (t & mask) ? (p0 + p1) : 0.0f;
        }
        #pragma unroll
        for (int o = 16; o > 0; o >>= 1) v += __shfl_xor_sync(0xffffffffu, v, o);
        if (lane == 0) wsum[warp][q] = v;
    }
    __syncthreads();
    if (t < NQ) {
        float s = 0.0f;
        #pragma unroll
        for (int w = 0; w < 16; w++) s += wsum[w][t];
        g_z[t] = 1.0f - 2.0f * s;
    }
    __syncthreads();
    if (t == 0) {
        __threadfence();
        atomicMax(&g_zflag, target);   // release; monotonic
    }
}

// ---------------------------------------------------------------------------
// Kernel C: broadcast fill — 64MB of float4 stores (proven 11.5us engine).
// ---------------------------------------------------------------------------
__global__ void __launch_bounds__(256)
fill_kernel(float4* __restrict__ out) {
    const int col = threadIdx.x;
    const float4 v = ((const float4*)g_y)[col];
    const size_t base = (size_t)blockIdx.x * 4;
    #pragma unroll
    for (int r = 0; r < 4; r++) {
        out[(base + r) * (EDIM / 4) + col] = v;
    }
}

// ---------------------------------------------------------------------------
// inputs: 0=x, 1=W_in, 2=b_in, 3=params, 4=W1, 5=b1, 6=W2, 7=b2
// x / W_in / b_in are dead in the reference.
// ---------------------------------------------------------------------------
extern "C" void kernel_launch(void* const* d_in, const int* in_sizes, int n_in,
                              void* d_out, int out_size) {
    const float* params = (const float*)d_in[3];
    const float* W1     = (const float*)d_in[4];
    const float* b1     = (const float*)d_in[5];
    const float* W2     = (const float*)d_in[6];
    const float* b2     = (const float*)d_in[7];
    float* out = (float*)d_out;

    circuit_h_y_kernel<<<GRID_A, 512>>>(params, W1, b1, W2, b2);
    fill_kernel<<<NTOK / 4, 256>>>((float4*)out);
}